// round 8
// baseline (speedup 1.0000x reference)
#include <cuda_runtime.h>
#include <cuda_bf16.h>
#include <cuda_fp16.h>
#include <cstdint>

// ============================================================================
// AWAttention on B200, baseline sm_100 mma.sync path.
//   Q = A@Wq^T + bq ; K = X@Wk^T + bk ; S = Q@K^T ; P = softmax(S) ; O = P@X
// GEMM mainloop: register-double-buffered fragments with LDSM interleaved
// among MMA groups (overlaps LSU and tensor pipes within each warp).
//   ABM=0: split-bf16 3-MMA (hh+hl+lh), 256 thr, 64x32 warp tiles
//   ABM=2: plain fp16 1-MMA,            512 thr, 32x32 warp tiles
// OUT modes: 0 = fp32 C ; 1 = split-bf16 (Chi,Clo) epilogue (Q/K).
// ============================================================================

#define SWZ(x) ((x) ^ (((x) >> 3) & 0x70))

__device__ __forceinline__ uint32_t smem_u32(const void* p) {
    uint32_t a;
    asm("{ .reg .u64 t; cvta.to.shared.u64 t, %1; cvt.u32.u64 %0, t; }" : "=r"(a) : "l"(p));
    return a;
}

#define CP_ASYNC16(sm, gm) \
    asm volatile("cp.async.cg.shared.global [%0], [%1], 16;" :: "r"(sm), "l"(gm))
#define CP_COMMIT() asm volatile("cp.async.commit_group;" ::: "memory")

__device__ __forceinline__ void ldmx4(uint32_t r[4], uint32_t addr) {
    asm volatile("ldmatrix.sync.aligned.m8n8.x4.shared.b16 {%0,%1,%2,%3}, [%4];"
                 : "=r"(r[0]), "=r"(r[1]), "=r"(r[2]), "=r"(r[3]) : "r"(addr));
}

__device__ __forceinline__ void mma_bf16(float c[4], const uint32_t a[4],
                                         uint32_t b0, uint32_t b1) {
    asm volatile(
        "mma.sync.aligned.m16n8k16.row.col.f32.bf16.bf16.f32 "
        "{%0,%1,%2,%3}, {%4,%5,%6,%7}, {%8,%9}, {%0,%1,%2,%3};"
        : "+f"(c[0]), "+f"(c[1]), "+f"(c[2]), "+f"(c[3])
        : "r"(a[0]), "r"(a[1]), "r"(a[2]), "r"(a[3]), "r"(b0), "r"(b1));
}

__device__ __forceinline__ void mma_f16(float c[4], const uint32_t a[4],
                                        uint32_t b0, uint32_t b1) {
    asm volatile(
        "mma.sync.aligned.m16n8k16.row.col.f32.f16.f16.f32 "
        "{%0,%1,%2,%3}, {%4,%5,%6,%7}, {%8,%9}, {%0,%1,%2,%3};"
        : "+f"(c[0]), "+f"(c[1]), "+f"(c[2]), "+f"(c[3])
        : "r"(a[0]), "r"(a[1]), "r"(a[2]), "r"(a[3]), "r"(b0), "r"(b1));
}

static constexpr int TILE_BYTES = 128 * 128;  // 128 rows x 128B (64 x 16-bit)

// ABM=0: 4 tiles/stage (Ah,Al,Bh,Bl), 3 stages -> 192KB, 256 threads
// ABM=2: 2 tiles/stage (Ah,Bh),       6 stages -> 192KB, 512 threads
template <int ABM> struct Cfg {
    static constexpr int NT  = (ABM == 0) ? 4 : 2;
    static constexpr int STG = (ABM == 0) ? 3 : 6;
    static constexpr int THREADS = (ABM == 0) ? 256 : 512;
    static constexpr int MI  = (ABM == 0) ? 4 : 2;  // 16-row m-tiles per warp
    static constexpr int STAGE_B = NT * TILE_BYTES;
    static constexpr int SMEM = STG * STAGE_B;
};

template <int ABM>
__device__ __forceinline__ void load_chunk(
    uint32_t stage, const uint16_t* __restrict__ Ah, const uint16_t* __restrict__ Al,
    const uint16_t* __restrict__ Bh, const uint16_t* __restrict__ Bl,
    int m0, int n0, int kc, int K, int tid)
{
    constexpr int THREADS = Cfg<ABM>::THREADS;
#pragma unroll
    for (int i = 0; i < 1024 / THREADS; ++i) {
        int ch  = tid + i * THREADS;  // 0..1023
        int row = ch >> 3;
        int c16 = ch & 7;
        uint32_t soff = SWZ((uint32_t)(row * 128 + c16 * 16));
        size_t ga = ((size_t)(m0 + row) * K + (size_t)kc * 64) * 2 + (size_t)c16 * 16;
        size_t gb = ((size_t)(n0 + row) * K + (size_t)kc * 64) * 2 + (size_t)c16 * 16;
        if (ABM == 0) {
            CP_ASYNC16(stage + 0 * TILE_BYTES + soff, (const char*)Ah + ga);
            CP_ASYNC16(stage + 1 * TILE_BYTES + soff, (const char*)Al + ga);
            CP_ASYNC16(stage + 2 * TILE_BYTES + soff, (const char*)Bh + gb);
            CP_ASYNC16(stage + 3 * TILE_BYTES + soff, (const char*)Bl + gb);
        } else {
            CP_ASYNC16(stage + 0 * TILE_BYTES + soff, (const char*)Ah + ga);
            CP_ASYNC16(stage + 1 * TILE_BYTES + soff, (const char*)Bh + gb);
        }
    }
}

template <int ABM, int OUTM>
__global__ void __launch_bounds__(Cfg<ABM>::THREADS, 1) gemm_kernel(
    const uint16_t* __restrict__ Ah, const uint16_t* __restrict__ Al,
    const uint16_t* __restrict__ Bh, const uint16_t* __restrict__ Bl,
    float* __restrict__ C, __nv_bfloat16* __restrict__ Chi,
    __nv_bfloat16* __restrict__ Clo, int M, int N, int K,
    const float* __restrict__ bias)
{
    constexpr int STG = Cfg<ABM>::STG;
    constexpr int STAGE_B = Cfg<ABM>::STAGE_B;
    constexpr int MI = Cfg<ABM>::MI;

    extern __shared__ __align__(1024) unsigned char smem[];
    uint32_t sbase = smem_u32(smem);
    int tid = threadIdx.x, wid = tid >> 5, lane = tid & 31;
    // ABM=0: 2 warps over M (64 rows), 4 over N (32 cols). ABM=2: 4 over M, 4 over N.
    int a_row0 = (ABM == 0) ? (wid & 1) * 64 : (wid & 3) * 32;
    int n_off  = ((ABM == 0) ? (wid >> 1) : (wid >> 2)) * 32;
    int m0 = blockIdx.y * 128, n0 = blockIdx.x * 128;

    float acc[MI][4][4];
#pragma unroll
    for (int i = 0; i < MI; ++i)
#pragma unroll
        for (int j = 0; j < 4; ++j)
#pragma unroll
            for (int e = 0; e < 4; ++e) acc[i][j][e] = 0.0f;

    const int nch = K >> 6;

#pragma unroll
    for (int s = 0; s < STG - 1; ++s) {
        if (s < nch)
            load_chunk<ABM>(sbase + s * STAGE_B, Ah, Al, Bh, Bl, m0, n0, s, K, tid);
        CP_COMMIT();
    }

    const int a_rowbase = a_row0 + (lane & 15);
    const int a_colb    = (lane >> 4) * 16;
    const int b_rowbase = n_off + (lane & 7) + ((lane >> 3) & 1) * 8;
    const int b_colb    = (lane >> 4) * 16;

    // Double-buffered register fragments
    uint32_t ahf[2][MI][4], alf[2][MI][4];  // alf unused for ABM=2
    uint32_t bhf[2][4][2], blf[2][4][2];    // blf unused for ABM=2

    for (int c = 0; c < nch; ++c) {
        if constexpr (STG == 3)      asm volatile("cp.async.wait_group 1;" ::: "memory");
        else                         asm volatile("cp.async.wait_group 4;" ::: "memory");
        __syncthreads();

        int nextc = c + STG - 1;
        if (nextc < nch)
            load_chunk<ABM>(sbase + (uint32_t)(nextc % STG) * STAGE_B,
                            Ah, Al, Bh, Bl, m0, n0, nextc, K, tid);
        CP_COMMIT();

        uint32_t st = sbase + (uint32_t)(c % STG) * STAGE_B;
        uint32_t tAh = st;
        uint32_t tAl = st + TILE_BYTES;                       // ABM=0 only
        uint32_t tBh = st + ((ABM == 0) ? 2 : 1) * TILE_BYTES;
        uint32_t tBl = st + 3 * TILE_BYTES;                   // ABM=0 only

        // Fragment load helpers (compile-time buf index via unrolled callers)
        #define LD_AH(buf, i, kk) \
            ldmx4(ahf[buf][i], tAh + SWZ((uint32_t)((a_rowbase + (i) * 16) * 128 + (kk) * 32 + a_colb)))
        #define LD_AL(buf, i, kk) \
            ldmx4(alf[buf][i], tAl + SWZ((uint32_t)((a_rowbase + (i) * 16) * 128 + (kk) * 32 + a_colb)))
        #define LD_BH(buf, jb, kk) do {                                               \
            uint32_t r_[4];                                                           \
            ldmx4(r_, tBh + SWZ((uint32_t)((b_rowbase + (jb) * 16) * 128 + (kk) * 32 + b_colb))); \
            bhf[buf][(jb) * 2 + 0][0] = r_[0]; bhf[buf][(jb) * 2 + 0][1] = r_[2];     \
            bhf[buf][(jb) * 2 + 1][0] = r_[1]; bhf[buf][(jb) * 2 + 1][1] = r_[3];     \
        } while (0)
        #define LD_BL(buf, jb, kk) do {                                               \
            uint32_t r_[4];                                                           \
            ldmx4(r_, tBl + SWZ((uint32_t)((b_rowbase + (jb) * 16) * 128 + (kk) * 32 + b_colb))); \
            blf[buf][(jb) * 2 + 0][0] = r_[0]; blf[buf][(jb) * 2 + 0][1] = r_[2];     \
            blf[buf][(jb) * 2 + 1][0] = r_[1]; blf[buf][(jb) * 2 + 1][1] = r_[3];     \
        } while (0)

        // Prologue: fill buffer 0 with ks=0 fragments
        if (ABM == 0) {
            LD_BH(0, 0, 0); LD_BH(0, 1, 0);
            LD_BL(0, 0, 0); LD_BL(0, 1, 0);
#pragma unroll
            for (int i = 0; i < MI; ++i) LD_AH(0, i, 0);
#pragma unroll
            for (int i = 0; i < MI; ++i) LD_AL(0, i, 0);
        } else {
            LD_BH(0, 0, 0); LD_BH(0, 1, 0);
#pragma unroll
            for (int i = 0; i < MI; ++i) LD_AH(0, i, 0);
        }

#pragma unroll
        for (int ks = 0; ks < 4; ++ks) {
            const int cb = ks & 1, nb = cb ^ 1;
            const bool pre = (ks < 3);
            const int nk = ks + 1;
            if (ABM == 0) {
                // j-group 0: 12 MMAs, then 3 next-ks loads
#pragma unroll
                for (int i = 0; i < MI; ++i) {
                    mma_bf16(acc[i][0], ahf[cb][i], bhf[cb][0][0], bhf[cb][0][1]);
                    mma_bf16(acc[i][0], ahf[cb][i], blf[cb][0][0], blf[cb][0][1]);
                    mma_bf16(acc[i][0], alf[cb][i], bhf[cb][0][0], bhf[cb][0][1]);
                }
                if (pre) { LD_BH(nb, 0, nk); LD_BH(nb, 1, nk); LD_BL(nb, 0, nk); }
                // j-group 1
#pragma unroll
                for (int i = 0; i < MI; ++i) {
                    mma_bf16(acc[i][1], ahf[cb][i], bhf[cb][1][0], bhf[cb][1][1]);
                    mma_bf16(acc[i][1], ahf[cb][i], blf[cb][1][0], blf[cb][1][1]);
                    mma_bf16(acc[i][1], alf[cb][i], bhf[cb][1][0], bhf[cb][1][1]);
                }
                if (pre) { LD_BL(nb, 1, nk); LD_AH(nb, 0, nk); LD_AH(nb, 1, nk); }
                // j-group 2
#pragma unroll
                for (int i = 0; i < MI; ++i) {
                    mma_bf16(acc[i][2], ahf[cb][i], bhf[cb][2][0], bhf[cb][2][1]);
                    mma_bf16(acc[i][2], ahf[cb][i], blf[cb][2][0], blf[cb][2][1]);
                    mma_bf16(acc[i][2], alf[cb][i], bhf[cb][2][0], bhf[cb][2][1]);
                }
                if (pre) { LD_AH(nb, 2, nk); LD_AH(nb, 3, nk); LD_AL(nb, 0, nk); }
                // j-group 3
#pragma unroll
                for (int i = 0; i < MI; ++i) {
                    mma_bf16(acc[i][3], ahf[cb][i], bhf[cb][3][0], bhf[cb][3][1]);
                    mma_bf16(acc[i][3], ahf[cb][i], blf[cb][3][0], blf[cb][3][1]);
                    mma_bf16(acc[i][3], alf[cb][i], bhf[cb][3][0], bhf[cb][3][1]);
                }
                if (pre) { LD_AL(nb, 1, nk); LD_AL(nb, 2, nk); LD_AL(nb, 3, nk); }
            } else {
#pragma unroll
                for (int i = 0; i < MI; ++i)
                    mma_f16(acc[i][0], ahf[cb][i], bhf[cb][0][0], bhf[cb][0][1]);
                if (pre) LD_BH(nb, 0, nk);
#pragma unroll
                for (int i = 0; i < MI; ++i)
                    mma_f16(acc[i][1], ahf[cb][i], bhf[cb][1][0], bhf[cb][1][1]);
                if (pre) LD_BH(nb, 1, nk);
#pragma unroll
                for (int i = 0; i < MI; ++i)
                    mma_f16(acc[i][2], ahf[cb][i], bhf[cb][2][0], bhf[cb][2][1]);
                if (pre) LD_AH(nb, 0, nk);
#pragma unroll
                for (int i = 0; i < MI; ++i)
                    mma_f16(acc[i][3], ahf[cb][i], bhf[cb][3][0], bhf[cb][3][1]);
                if (pre) LD_AH(nb, 1, nk);
            }
        }
        #undef LD_AH
        #undef LD_AL
        #undef LD_BH
        #undef LD_BL
        __syncthreads();
    }

    // Epilogue
    int g = lane >> 2, t = lane & 3;
#pragma unroll
    for (int i = 0; i < MI; ++i) {
        int r0 = m0 + a_row0 + i * 16 + g;
#pragma unroll
        for (int j = 0; j < 4; ++j) {
            int col = n0 + n_off + j * 8 + t * 2;
            float b0 = 0.0f, b1 = 0.0f;
            if (bias) { b0 = __ldg(bias + col); b1 = __ldg(bias + col + 1); }
            float v0 = acc[i][j][0] + b0, v1 = acc[i][j][1] + b1;
            float v2 = acc[i][j][2] + b0, v3 = acc[i][j][3] + b1;
            if constexpr (OUTM == 0) {
                *(float2*)(C + (size_t)r0 * N + col)       = make_float2(v0, v1);
                *(float2*)(C + (size_t)(r0 + 8) * N + col) = make_float2(v2, v3);
            } else {
                __nv_bfloat16 h0 = __float2bfloat16(v0), h1 = __float2bfloat16(v1);
                __nv_bfloat16 h2 = __float2bfloat16(v2), h3 = __float2bfloat16(v3);
                __nv_bfloat16 l0 = __float2bfloat16(v0 - __bfloat162float(h0));
                __nv_bfloat16 l1 = __float2bfloat16(v1 - __bfloat162float(h1));
                __nv_bfloat16 l2 = __float2bfloat16(v2 - __bfloat162float(h2));
                __nv_bfloat16 l3 = __float2bfloat16(v3 - __bfloat162float(h3));
                __nv_bfloat162 hh0; hh0.x = h0; hh0.y = h1;
                __nv_bfloat162 hh1; hh1.x = h2; hh1.y = h3;
                __nv_bfloat162 ll0; ll0.x = l0; ll0.y = l1;
                __nv_bfloat162 ll1; ll1.x = l2; ll1.y = l3;
                *(__nv_bfloat162*)(Chi + (size_t)r0 * N + col)       = hh0;
                *(__nv_bfloat162*)(Chi + (size_t)(r0 + 8) * N + col) = hh1;
                *(__nv_bfloat162*)(Clo + (size_t)r0 * N + col)       = ll0;
                *(__nv_bfloat162*)(Clo + (size_t)(r0 + 8) * N + col) = ll1;
            }
        }
    }
}

// ---------------------------------------------------------------------------
// Fused fp32 -> (bf16 hi, bf16 lo) split for A, Wq, Wk (one launch)
// ---------------------------------------------------------------------------
__device__ __forceinline__ void split_one(const float* __restrict__ in,
                                          __nv_bfloat16* __restrict__ hi,
                                          __nv_bfloat16* __restrict__ lo,
                                          long long n, long long gtid, long long stride)
{
    for (long long i = gtid; i < n; i += stride) {
        float x = in[i];
        __nv_bfloat16 h = __float2bfloat16(x);
        hi[i] = h;
        lo[i] = __float2bfloat16(x - __bfloat162float(h));
    }
}

__global__ void fused_split_kernel(
    const float* __restrict__ A,  __nv_bfloat16* Ahi,  __nv_bfloat16* Alo,  long long nA,
    const float* __restrict__ W1, __nv_bfloat16* W1hi, __nv_bfloat16* W1lo,
    const float* __restrict__ W2, __nv_bfloat16* W2hi, __nv_bfloat16* W2lo, long long nW)
{
    long long gtid = (long long)blockIdx.x * blockDim.x + threadIdx.x;
    long long stride = (long long)gridDim.x * blockDim.x;
    split_one(A,  Ahi,  Alo,  nA, gtid, stride);
    split_one(W1, W1hi, W1lo, nW, gtid, stride);
    split_one(W2, W2hi, W2lo, nW, gtid, stride);
}

// ---------------------------------------------------------------------------
// X: one read -> (bf16 hi, bf16 lo) linear + fp16 transposed [C,R]
// ---------------------------------------------------------------------------
__global__ void xsplit_kernel(const float* __restrict__ X,
                              __nv_bfloat16* __restrict__ hi,
                              __nv_bfloat16* __restrict__ lo,
                              __half* __restrict__ xt, int R, int C)
{
    __shared__ float tbuf[32][33];
    int c0 = blockIdx.x * 32, r0 = blockIdx.y * 32;
    int tx = threadIdx.x, ty = threadIdx.y;  // 32 x 8
#pragma unroll
    for (int j = 0; j < 4; ++j) {
        int r = r0 + ty + 8 * j;
        float v = X[(long long)r * C + c0 + tx];
        tbuf[ty + 8 * j][tx] = v;
        __nv_bfloat16 h = __float2bfloat16(v);
        hi[(long long)r * C + c0 + tx] = h;
        lo[(long long)r * C + c0 + tx] = __float2bfloat16(v - __bfloat162float(h));
    }
    __syncthreads();
#pragma unroll
    for (int j = 0; j < 4; ++j) {
        float v = tbuf[tx][ty + 8 * j];  // X[r0+tx][c0+ty+8j]
        xt[(long long)(c0 + ty + 8 * j) * R + r0 + tx] = __float2half(v);
    }
}

// ---------------------------------------------------------------------------
// Row softmax (N=8192) writing fp16 probabilities (single S read via smem buf)
// ---------------------------------------------------------------------------
__global__ void __launch_bounds__(256) softmax_kernel(
    const float* __restrict__ S, __half* __restrict__ P, int N)
{
    __shared__ float buf[8192];
    __shared__ float red[8];
    int row = blockIdx.x, tid = threadIdx.x;
    const float* s = S + (long long)row * N;

    float mx = -3.0e38f;
    for (int i = tid; i < N; i += 256) mx = fmaxf(mx, s[i]);
#pragma unroll
    for (int o = 16; o; o >>= 1) mx = fmaxf(mx, __shfl_xor_sync(0xFFFFFFFFu, mx, o));
    if ((tid & 31) == 0) red[tid >> 5] = mx;
    __syncthreads();
    mx = red[0];
#pragma unroll
    for (int w = 1; w < 8; ++w) mx = fmaxf(mx, red[w]);

    float sum = 0.0f;
    for (int i = tid; i < N; i += 256) {
        float e = __expf(s[i] - mx);
        buf[i] = e;
        sum += e;
    }
#pragma unroll
    for (int o = 16; o; o >>= 1) sum += __shfl_xor_sync(0xFFFFFFFFu, sum, o);
    __syncthreads();
    if ((tid & 31) == 0) red[tid >> 5] = sum;
    __syncthreads();
    sum = 0.0f;
#pragma unroll
    for (int w = 0; w < 8; ++w) sum += red[w];
    float inv = 1.0f / sum;

    for (int i = tid; i < N; i += 256)
        P[(long long)row * N + i] = __float2half(buf[i] * inv);
}

// ---------------------------------------------------------------------------
// Scratch
// ---------------------------------------------------------------------------
static constexpr size_t SZ_AX = (size_t)8192 * 1024;
static constexpr size_t SZ_W  = (size_t)512 * 1024;
static constexpr size_t SZ_QK = (size_t)8192 * 512;
static constexpr size_t SZ_S  = (size_t)8192 * 8192;

static constexpr size_t OFF_AHI  = 0;
static constexpr size_t OFF_ALO  = OFF_AHI  + SZ_AX * 2;
static constexpr size_t OFF_XHI  = OFF_ALO  + SZ_AX * 2;
static constexpr size_t OFF_XLO  = OFF_XHI  + SZ_AX * 2;
static constexpr size_t OFF_WQHI = OFF_XLO  + SZ_AX * 2;
static constexpr size_t OFF_WQLO = OFF_WQHI + SZ_W * 2;
static constexpr size_t OFF_WKHI = OFF_WQLO + SZ_W * 2;
static constexpr size_t OFF_WKLO = OFF_WKHI + SZ_W * 2;
static constexpr size_t OFF_QHI  = OFF_WKLO + SZ_W * 2;
static constexpr size_t OFF_QLO  = OFF_QHI  + SZ_QK * 2;
static constexpr size_t OFF_KHI  = OFF_QLO  + SZ_QK * 2;
static constexpr size_t OFF_KLO  = OFF_KHI  + SZ_QK * 2;
static constexpr size_t OFF_S    = OFF_KLO  + SZ_QK * 2;
static constexpr size_t OFF_PHI  = OFF_S    + SZ_S * 4;
static constexpr size_t OFF_XTHI = OFF_PHI  + SZ_S * 2;
static constexpr size_t SCRATCH_TOTAL = OFF_XTHI + SZ_AX * 2;

__device__ __align__(256) unsigned char g_scratch[SCRATCH_TOTAL];

// ---------------------------------------------------------------------------
// kernel_launch
// ---------------------------------------------------------------------------
extern "C" void kernel_launch(void* const* d_in, const int* in_sizes, int n_in,
                              void* d_out, int out_size)
{
    const float* A  = (const float*)d_in[0];
    const float* X  = (const float*)d_in[1];
    const float* Wq = (const float*)d_in[2];
    const float* bq = (const float*)d_in[3];
    const float* Wk = (const float*)d_in[4];
    const float* bk = (const float*)d_in[5];
    float* out = (float*)d_out;

    unsigned char* s = nullptr;
    cudaGetSymbolAddress((void**)&s, g_scratch);
    auto BF = [&](size_t off) { return (__nv_bfloat16*)(s + off); };
    auto U16 = [&](size_t off) { return (const uint16_t*)(s + off); };
    auto F  = [&](size_t off) { return (float*)(s + off); };

    cudaFuncSetAttribute(gemm_kernel<0, 0>,
                         cudaFuncAttributeMaxDynamicSharedMemorySize, Cfg<0>::SMEM);
    cudaFuncSetAttribute(gemm_kernel<0, 1>,
                         cudaFuncAttributeMaxDynamicSharedMemorySize, Cfg<0>::SMEM);
    cudaFuncSetAttribute(gemm_kernel<2, 0>,
                         cudaFuncAttributeMaxDynamicSharedMemorySize, Cfg<2>::SMEM);

    // Splits: A/Wq/Wk (one launch) ; X -> hi/lo + fp16 transpose (one launch)
    fused_split_kernel<<<2048, 256>>>(
        A,  BF(OFF_AHI),  BF(OFF_ALO),  (long long)SZ_AX,
        Wq, BF(OFF_WQHI), BF(OFF_WQLO),
        Wk, BF(OFF_WKHI), BF(OFF_WKLO), (long long)SZ_W);
    xsplit_kernel<<<dim3(1024 / 32, 8192 / 32), dim3(32, 8)>>>(
        X, BF(OFF_XHI), BF(OFF_XLO), (__half*)(s + OFF_XTHI), 8192, 1024);

    // Q/K GEMMs with fused split-bf16 epilogue (M=8192, N=512, K=1024)
    dim3 gq(512 / 128, 8192 / 128);
    gemm_kernel<0, 1><<<gq, Cfg<0>::THREADS, Cfg<0>::SMEM>>>(
        U16(OFF_AHI), U16(OFF_ALO), U16(OFF_WQHI), U16(OFF_WQLO),
        nullptr, BF(OFF_QHI), BF(OFF_QLO), 8192, 512, 1024, bq);
    gemm_kernel<0, 1><<<gq, Cfg<0>::THREADS, Cfg<0>::SMEM>>>(
        U16(OFF_XHI), U16(OFF_XLO), U16(OFF_WKHI), U16(OFF_WKLO),
        nullptr, BF(OFF_KHI), BF(OFF_KLO), 8192, 512, 1024, bk);

    // S = Q @ K^T   (M=8192, N=8192, K=512)
    dim3 gs(8192 / 128, 8192 / 128);
    gemm_kernel<0, 0><<<gs, Cfg<0>::THREADS, Cfg<0>::SMEM>>>(
        U16(OFF_QHI), U16(OFF_QLO), U16(OFF_KHI), U16(OFF_KLO),
        F(OFF_S), nullptr, nullptr, 8192, 8192, 512, nullptr);

    // P = softmax(S) -> fp16
    softmax_kernel<<<8192, 256>>>(F(OFF_S), (__half*)(s + OFF_PHI), 8192);

    // O = P @ X   (M=8192, N=1024, K=8192), single fp16 MMA
    dim3 go(1024 / 128, 8192 / 128);
    gemm_kernel<2, 0><<<go, Cfg<2>::THREADS, Cfg<2>::SMEM>>>(
        U16(OFF_PHI), nullptr, U16(OFF_XTHI), nullptr,
        out, nullptr, nullptr, 8192, 1024, 8192, nullptr);
}

// round 9
// speedup vs baseline: 1.0272x; 1.0272x over previous
#include <cuda_runtime.h>
#include <cuda_bf16.h>
#include <cuda_fp16.h>
#include <cstdint>

// ============================================================================
// AWAttention on B200, baseline sm_100 mma.sync path.
//   Q = A@Wq^T + bq ; K = X@Wk^T + bk ; S = Q@K^T ; P = softmax(S) ; O = P@X
// Precision scheme (fp16 hi+lo split, 22 mantissa bits):
//   ABM=0 (Q/K/S): hh term -> fp32-acc MMA ; hl+lh -> fp16-acc MMA (full rate),
//                  combined in epilogue. Missing ll term ~2^-24 (negligible).
//   ABM=2 (O):     P_fp16 @ Xhi_fp16, fp32 acc (long sums need fp32).
// OUT modes: 0 = fp32 C ; 1 = split-fp16 (Chi,Clo) epilogue (Q/K).
// ============================================================================

#define SWZ(x) ((x) ^ (((x) >> 3) & 0x70))

__device__ __forceinline__ uint32_t smem_u32(const void* p) {
    uint32_t a;
    asm("{ .reg .u64 t; cvta.to.shared.u64 t, %1; cvt.u32.u64 %0, t; }" : "=r"(a) : "l"(p));
    return a;
}

#define CP_ASYNC16(sm, gm) \
    asm volatile("cp.async.cg.shared.global [%0], [%1], 16;" :: "r"(sm), "l"(gm))
#define CP_COMMIT() asm volatile("cp.async.commit_group;" ::: "memory")

__device__ __forceinline__ void ldmx4(uint32_t r[4], uint32_t addr) {
    asm volatile("ldmatrix.sync.aligned.m8n8.x4.shared.b16 {%0,%1,%2,%3}, [%4];"
                 : "=r"(r[0]), "=r"(r[1]), "=r"(r[2]), "=r"(r[3]) : "r"(addr));
}

// fp16 operands, fp32 accumulator
__device__ __forceinline__ void mma_f16(float c[4], const uint32_t a[4],
                                        uint32_t b0, uint32_t b1) {
    asm volatile(
        "mma.sync.aligned.m16n8k16.row.col.f32.f16.f16.f32 "
        "{%0,%1,%2,%3}, {%4,%5,%6,%7}, {%8,%9}, {%0,%1,%2,%3};"
        : "+f"(c[0]), "+f"(c[1]), "+f"(c[2]), "+f"(c[3])
        : "r"(a[0]), "r"(a[1]), "r"(a[2]), "r"(a[3]), "r"(b0), "r"(b1));
}

// fp16 operands, fp16 accumulator (2 x half2 regs) — full-rate hypothesis
__device__ __forceinline__ void mma_f16a(uint32_t c[2], const uint32_t a[4],
                                         uint32_t b0, uint32_t b1) {
    asm volatile(
        "mma.sync.aligned.m16n8k16.row.col.f16.f16.f16.f16 "
        "{%0,%1}, {%2,%3,%4,%5}, {%6,%7}, {%0,%1};"
        : "+r"(c[0]), "+r"(c[1])
        : "r"(a[0]), "r"(a[1]), "r"(a[2]), "r"(a[3]), "r"(b0), "r"(b1));
}

static constexpr int TILE_BYTES = 128 * 128;  // 128 rows x 128B (64 x 16-bit)

// ABM=0: 4 tiles/stage (Ah,Al,Bh,Bl), 3 stages -> 192KB
// ABM=2: 2 tiles/stage (Ah,Bh),       6 stages -> 192KB
template <int ABM> struct Cfg {
    static constexpr int NT  = (ABM == 0) ? 4 : 2;
    static constexpr int STG = (ABM == 0) ? 3 : 6;
    static constexpr int STAGE_B = NT * TILE_BYTES;
    static constexpr int SMEM = STG * STAGE_B;
};

template <int ABM>
__device__ __forceinline__ void load_chunk(
    uint32_t stage, const uint16_t* __restrict__ Ah, const uint16_t* __restrict__ Al,
    const uint16_t* __restrict__ Bh, const uint16_t* __restrict__ Bl,
    int m0, int n0, int kc, int K, int tid)
{
#pragma unroll
    for (int i = 0; i < 2; ++i) {
        int ch  = tid + i * 512;  // 0..1023
        int row = ch >> 3;
        int c16 = ch & 7;
        uint32_t soff = SWZ((uint32_t)(row * 128 + c16 * 16));
        size_t ga = ((size_t)(m0 + row) * K + (size_t)kc * 64) * 2 + (size_t)c16 * 16;
        size_t gb = ((size_t)(n0 + row) * K + (size_t)kc * 64) * 2 + (size_t)c16 * 16;
        if (ABM == 0) {
            CP_ASYNC16(stage + 0 * TILE_BYTES + soff, (const char*)Ah + ga);
            CP_ASYNC16(stage + 1 * TILE_BYTES + soff, (const char*)Al + ga);
            CP_ASYNC16(stage + 2 * TILE_BYTES + soff, (const char*)Bh + gb);
            CP_ASYNC16(stage + 3 * TILE_BYTES + soff, (const char*)Bl + gb);
        } else {
            CP_ASYNC16(stage + 0 * TILE_BYTES + soff, (const char*)Ah + ga);
            CP_ASYNC16(stage + 1 * TILE_BYTES + soff, (const char*)Bh + gb);
        }
    }
}

template <int ABM, int OUTM>
__global__ void __launch_bounds__(512, 1) gemm_kernel(
    const uint16_t* __restrict__ Ah, const uint16_t* __restrict__ Al,
    const uint16_t* __restrict__ Bh, const uint16_t* __restrict__ Bl,
    float* __restrict__ C, __half* __restrict__ Chi,
    __half* __restrict__ Clo, int M, int N, int K,
    const float* __restrict__ bias)
{
    constexpr int STG = Cfg<ABM>::STG;
    constexpr int STAGE_B = Cfg<ABM>::STAGE_B;

    extern __shared__ __align__(1024) unsigned char smem[];
    uint32_t sbase = smem_u32(smem);
    int tid = threadIdx.x, wid = tid >> 5, lane = tid & 31;
    int warp_m = wid & 3;   // 4 warps over M -> 32 rows each
    int warp_n = wid >> 2;  // 4 warps over N -> 32 cols each
    int m0 = blockIdx.y * 128, n0 = blockIdx.x * 128;

    float acc[2][4][4];
    uint32_t crs[2][4][2];  // fp16 cross-term accumulators (ABM=0 only)
#pragma unroll
    for (int i = 0; i < 2; ++i)
#pragma unroll
        for (int j = 0; j < 4; ++j) {
#pragma unroll
            for (int e = 0; e < 4; ++e) acc[i][j][e] = 0.0f;
            crs[i][j][0] = 0u; crs[i][j][1] = 0u;
        }

    const int nch = K >> 6;

#pragma unroll
    for (int s = 0; s < STG - 1; ++s) {
        if (s < nch)
            load_chunk<ABM>(sbase + s * STAGE_B, Ah, Al, Bh, Bl, m0, n0, s, K, tid);
        CP_COMMIT();
    }

    const int a_rowbase = warp_m * 32 + (lane & 15);
    const int a_colb    = (lane >> 4) * 16;
    const int b_rowbase = warp_n * 32 + (lane & 7) + ((lane >> 3) & 1) * 8;
    const int b_colb    = (lane >> 4) * 16;

    for (int c = 0; c < nch; ++c) {
        if constexpr (STG == 3)      asm volatile("cp.async.wait_group 1;" ::: "memory");
        else                         asm volatile("cp.async.wait_group 4;" ::: "memory");
        __syncthreads();

        int nextc = c + STG - 1;
        if (nextc < nch)
            load_chunk<ABM>(sbase + (uint32_t)(nextc % STG) * STAGE_B,
                            Ah, Al, Bh, Bl, m0, n0, nextc, K, tid);
        CP_COMMIT();

        uint32_t st = sbase + (uint32_t)(c % STG) * STAGE_B;

#pragma unroll
        for (int ks = 0; ks < 4; ++ks) {
            if (ABM == 0) {
                uint32_t tAh = st, tAl = st + TILE_BYTES;
                uint32_t tBh = st + 2 * TILE_BYTES, tBl = st + 3 * TILE_BYTES;
                uint32_t ah[2][4], al[2][4];
#pragma unroll
                for (int i = 0; i < 2; ++i) {
                    uint32_t off = SWZ((uint32_t)((a_rowbase + i * 16) * 128 + ks * 32 + a_colb));
                    ldmx4(ah[i], tAh + off);
                    ldmx4(al[i], tAl + off);
                }
                uint32_t bh[4][2], bl[4][2];
#pragma unroll
                for (int jb = 0; jb < 2; ++jb) {
                    uint32_t off = SWZ((uint32_t)((b_rowbase + jb * 16) * 128 + ks * 32 + b_colb));
                    uint32_t r[4];
                    ldmx4(r, tBh + off);
                    bh[jb * 2 + 0][0] = r[0]; bh[jb * 2 + 0][1] = r[2];
                    bh[jb * 2 + 1][0] = r[1]; bh[jb * 2 + 1][1] = r[3];
                    ldmx4(r, tBl + off);
                    bl[jb * 2 + 0][0] = r[0]; bl[jb * 2 + 0][1] = r[2];
                    bl[jb * 2 + 1][0] = r[1]; bl[jb * 2 + 1][1] = r[3];
                }
#pragma unroll
                for (int i = 0; i < 2; ++i)
#pragma unroll
                    for (int j = 0; j < 4; ++j) {
                        mma_f16 (acc[i][j], ah[i], bh[j][0], bh[j][1]);  // hh (fp32 acc)
                        mma_f16a(crs[i][j], ah[i], bl[j][0], bl[j][1]);  // hl (fp16 acc)
                        mma_f16a(crs[i][j], al[i], bh[j][0], bh[j][1]);  // lh (fp16 acc)
                    }
            } else {
                uint32_t tAh = st;
                uint32_t tBh = st + TILE_BYTES;
                uint32_t ah[2][4];
#pragma unroll
                for (int i = 0; i < 2; ++i) {
                    uint32_t off = SWZ((uint32_t)((a_rowbase + i * 16) * 128 + ks * 32 + a_colb));
                    ldmx4(ah[i], tAh + off);
                }
                uint32_t bh[4][2];
#pragma unroll
                for (int jb = 0; jb < 2; ++jb) {
                    uint32_t off = SWZ((uint32_t)((b_rowbase + jb * 16) * 128 + ks * 32 + b_colb));
                    uint32_t r[4];
                    ldmx4(r, tBh + off);
                    bh[jb * 2 + 0][0] = r[0]; bh[jb * 2 + 0][1] = r[2];
                    bh[jb * 2 + 1][0] = r[1]; bh[jb * 2 + 1][1] = r[3];
                }
#pragma unroll
                for (int i = 0; i < 2; ++i)
#pragma unroll
                    for (int j = 0; j < 4; ++j)
                        mma_f16(acc[i][j], ah[i], bh[j][0], bh[j][1]);
            }
        }
        __syncthreads();
    }

    // Epilogue: combine fp32 hh acc + fp16 cross acc, then store.
    int g = lane >> 2, t = lane & 3;
#pragma unroll
    for (int i = 0; i < 2; ++i) {
        int r0 = m0 + warp_m * 32 + i * 16 + g;
#pragma unroll
        for (int j = 0; j < 4; ++j) {
            int col = n0 + warp_n * 32 + j * 8 + t * 2;
            float v0 = acc[i][j][0], v1 = acc[i][j][1];
            float v2 = acc[i][j][2], v3 = acc[i][j][3];
            if (ABM == 0) {
                __half2 c01 = *(__half2*)&crs[i][j][0];
                __half2 c23 = *(__half2*)&crs[i][j][1];
                v0 += __low2float(c01);  v1 += __high2float(c01);
                v2 += __low2float(c23);  v3 += __high2float(c23);
            }
            if (bias) {
                float b0 = __ldg(bias + col), b1 = __ldg(bias + col + 1);
                v0 += b0; v1 += b1; v2 += b0; v3 += b1;
            }
            if constexpr (OUTM == 0) {
                *(float2*)(C + (size_t)r0 * N + col)       = make_float2(v0, v1);
                *(float2*)(C + (size_t)(r0 + 8) * N + col) = make_float2(v2, v3);
            } else {
                __half h0 = __float2half(v0), h1 = __float2half(v1);
                __half h2 = __float2half(v2), h3 = __float2half(v3);
                __half l0 = __float2half(v0 - __half2float(h0));
                __half l1 = __float2half(v1 - __half2float(h1));
                __half l2 = __float2half(v2 - __half2float(h2));
                __half l3 = __float2half(v3 - __half2float(h3));
                __half2 hh0; hh0.x = h0; hh0.y = h1;
                __half2 hh1; hh1.x = h2; hh1.y = h3;
                __half2 ll0; ll0.x = l0; ll0.y = l1;
                __half2 ll1; ll1.x = l2; ll1.y = l3;
                *(__half2*)(Chi + (size_t)r0 * N + col)       = hh0;
                *(__half2*)(Chi + (size_t)(r0 + 8) * N + col) = hh1;
                *(__half2*)(Clo + (size_t)r0 * N + col)       = ll0;
                *(__half2*)(Clo + (size_t)(r0 + 8) * N + col) = ll1;
            }
        }
    }
}

// ---------------------------------------------------------------------------
// Fused fp32 -> (fp16 hi, fp16 lo) split for A, Wq, Wk (one launch)
// ---------------------------------------------------------------------------
__device__ __forceinline__ void split_one(const float* __restrict__ in,
                                          __half* __restrict__ hi,
                                          __half* __restrict__ lo,
                                          long long n, long long gtid, long long stride)
{
    for (long long i = gtid; i < n; i += stride) {
        float x = in[i];
        __half h = __float2half(x);
        hi[i] = h;
        lo[i] = __float2half(x - __half2float(h));
    }
}

__global__ void fused_split_kernel(
    const float* __restrict__ A,  __half* Ahi,  __half* Alo,  long long nA,
    const float* __restrict__ W1, __half* W1hi, __half* W1lo,
    const float* __restrict__ W2, __half* W2hi, __half* W2lo, long long nW)
{
    long long gtid = (long long)blockIdx.x * blockDim.x + threadIdx.x;
    long long stride = (long long)gridDim.x * blockDim.x;
    split_one(A,  Ahi,  Alo,  nA, gtid, stride);
    split_one(W1, W1hi, W1lo, nW, gtid, stride);
    split_one(W2, W2hi, W2lo, nW, gtid, stride);
}

// ---------------------------------------------------------------------------
// X: one read -> (fp16 hi, fp16 lo) linear + fp16 transposed [C,R]
// ---------------------------------------------------------------------------
__global__ void xsplit_kernel(const float* __restrict__ X,
                              __half* __restrict__ hi,
                              __half* __restrict__ lo,
                              __half* __restrict__ xt, int R, int C)
{
    __shared__ float tbuf[32][33];
    int c0 = blockIdx.x * 32, r0 = blockIdx.y * 32;
    int tx = threadIdx.x, ty = threadIdx.y;  // 32 x 8
#pragma unroll
    for (int j = 0; j < 4; ++j) {
        int r = r0 + ty + 8 * j;
        float v = X[(long long)r * C + c0 + tx];
        tbuf[ty + 8 * j][tx] = v;
        __half h = __float2half(v);
        hi[(long long)r * C + c0 + tx] = h;
        lo[(long long)r * C + c0 + tx] = __float2half(v - __half2float(h));
    }
    __syncthreads();
#pragma unroll
    for (int j = 0; j < 4; ++j) {
        float v = tbuf[tx][ty + 8 * j];  // X[r0+tx][c0+ty+8j]
        xt[(long long)(c0 + ty + 8 * j) * R + r0 + tx] = __float2half(v);
    }
}

// ---------------------------------------------------------------------------
// Row softmax (N=8192) writing fp16 probabilities (single S read via smem buf)
// ---------------------------------------------------------------------------
__global__ void __launch_bounds__(256) softmax_kernel(
    const float* __restrict__ S, __half* __restrict__ P, int N)
{
    __shared__ float buf[8192];
    __shared__ float red[8];
    int row = blockIdx.x, tid = threadIdx.x;
    const float* s = S + (long long)row * N;

    float mx = -3.0e38f;
    for (int i = tid; i < N; i += 256) mx = fmaxf(mx, s[i]);
#pragma unroll
    for (int o = 16; o; o >>= 1) mx = fmaxf(mx, __shfl_xor_sync(0xFFFFFFFFu, mx, o));
    if ((tid & 31) == 0) red[tid >> 5] = mx;
    __syncthreads();
    mx = red[0];
#pragma unroll
    for (int w = 1; w < 8; ++w) mx = fmaxf(mx, red[w]);

    float sum = 0.0f;
    for (int i = tid; i < N; i += 256) {
        float e = __expf(s[i] - mx);
        buf[i] = e;
        sum += e;
    }
#pragma unroll
    for (int o = 16; o; o >>= 1) sum += __shfl_xor_sync(0xFFFFFFFFu, sum, o);
    __syncthreads();
    if ((tid & 31) == 0) red[tid >> 5] = sum;
    __syncthreads();
    sum = 0.0f;
#pragma unroll
    for (int w = 0; w < 8; ++w) sum += red[w];
    float inv = 1.0f / sum;

    for (int i = tid; i < N; i += 256)
        P[(long long)row * N + i] = __float2half(buf[i] * inv);
}

// ---------------------------------------------------------------------------
// Scratch
// ---------------------------------------------------------------------------
static constexpr size_t SZ_AX = (size_t)8192 * 1024;
static constexpr size_t SZ_W  = (size_t)512 * 1024;
static constexpr size_t SZ_QK = (size_t)8192 * 512;
static constexpr size_t SZ_S  = (size_t)8192 * 8192;

static constexpr size_t OFF_AHI  = 0;
static constexpr size_t OFF_ALO  = OFF_AHI  + SZ_AX * 2;
static constexpr size_t OFF_XHI  = OFF_ALO  + SZ_AX * 2;
static constexpr size_t OFF_XLO  = OFF_XHI  + SZ_AX * 2;
static constexpr size_t OFF_WQHI = OFF_XLO  + SZ_AX * 2;
static constexpr size_t OFF_WQLO = OFF_WQHI + SZ_W * 2;
static constexpr size_t OFF_WKHI = OFF_WQLO + SZ_W * 2;
static constexpr size_t OFF_WKLO = OFF_WKHI + SZ_W * 2;
static constexpr size_t OFF_QHI  = OFF_WKLO + SZ_W * 2;
static constexpr size_t OFF_QLO  = OFF_QHI  + SZ_QK * 2;
static constexpr size_t OFF_KHI  = OFF_QLO  + SZ_QK * 2;
static constexpr size_t OFF_KLO  = OFF_KHI  + SZ_QK * 2;
static constexpr size_t OFF_S    = OFF_KLO  + SZ_QK * 2;
static constexpr size_t OFF_PHI  = OFF_S    + SZ_S * 4;
static constexpr size_t OFF_XTHI = OFF_PHI  + SZ_S * 2;
static constexpr size_t SCRATCH_TOTAL = OFF_XTHI + SZ_AX * 2;

__device__ __align__(256) unsigned char g_scratch[SCRATCH_TOTAL];

// ---------------------------------------------------------------------------
// kernel_launch
// ---------------------------------------------------------------------------
extern "C" void kernel_launch(void* const* d_in, const int* in_sizes, int n_in,
                              void* d_out, int out_size)
{
    const float* A  = (const float*)d_in[0];
    const float* X  = (const float*)d_in[1];
    const float* Wq = (const float*)d_in[2];
    const float* bq = (const float*)d_in[3];
    const float* Wk = (const float*)d_in[4];
    const float* bk = (const float*)d_in[5];
    float* out = (float*)d_out;

    unsigned char* s = nullptr;
    cudaGetSymbolAddress((void**)&s, g_scratch);
    auto H  = [&](size_t off) { return (__half*)(s + off); };
    auto U16 = [&](size_t off) { return (const uint16_t*)(s + off); };
    auto F  = [&](size_t off) { return (float*)(s + off); };

    cudaFuncSetAttribute(gemm_kernel<0, 0>,
                         cudaFuncAttributeMaxDynamicSharedMemorySize, Cfg<0>::SMEM);
    cudaFuncSetAttribute(gemm_kernel<0, 1>,
                         cudaFuncAttributeMaxDynamicSharedMemorySize, Cfg<0>::SMEM);
    cudaFuncSetAttribute(gemm_kernel<2, 0>,
                         cudaFuncAttributeMaxDynamicSharedMemorySize, Cfg<2>::SMEM);

    // Splits: A/Wq/Wk (one launch) ; X -> hi/lo + fp16 transpose (one launch)
    fused_split_kernel<<<2048, 256>>>(
        A,  H(OFF_AHI),  H(OFF_ALO),  (long long)SZ_AX,
        Wq, H(OFF_WQHI), H(OFF_WQLO),
        Wk, H(OFF_WKHI), H(OFF_WKLO), (long long)SZ_W);
    xsplit_kernel<<<dim3(1024 / 32, 8192 / 32), dim3(32, 8)>>>(
        X, H(OFF_XHI), H(OFF_XLO), H(OFF_XTHI), 8192, 1024);

    // Q/K GEMMs with fused split-fp16 epilogue (M=8192, N=512, K=1024)
    dim3 gq(512 / 128, 8192 / 128);
    gemm_kernel<0, 1><<<gq, 512, Cfg<0>::SMEM>>>(
        U16(OFF_AHI), U16(OFF_ALO), U16(OFF_WQHI), U16(OFF_WQLO),
        nullptr, H(OFF_QHI), H(OFF_QLO), 8192, 512, 1024, bq);
    gemm_kernel<0, 1><<<gq, 512, Cfg<0>::SMEM>>>(
        U16(OFF_XHI), U16(OFF_XLO), U16(OFF_WKHI), U16(OFF_WKLO),
        nullptr, H(OFF_KHI), H(OFF_KLO), 8192, 512, 1024, bk);

    // S = Q @ K^T   (M=8192, N=8192, K=512)
    dim3 gs(8192 / 128, 8192 / 128);
    gemm_kernel<0, 0><<<gs, 512, Cfg<0>::SMEM>>>(
        U16(OFF_QHI), U16(OFF_QLO), U16(OFF_KHI), U16(OFF_KLO),
        F(OFF_S), nullptr, nullptr, 8192, 8192, 512, nullptr);

    // P = softmax(S) -> fp16
    softmax_kernel<<<8192, 256>>>(F(OFF_S), (__half*)(s + OFF_PHI), 8192);

    // O = P @ X   (M=8192, N=1024, K=8192), single fp16 MMA (fp32 acc)
    dim3 go(1024 / 128, 8192 / 128);
    gemm_kernel<2, 0><<<go, 512, Cfg<2>::SMEM>>>(
        U16(OFF_PHI), nullptr, U16(OFF_XTHI), nullptr,
        out, nullptr, nullptr, 8192, 1024, 8192, nullptr);
}